// round 10
// baseline (speedup 1.0000x reference)
#include <cuda_runtime.h>

// ---------------------------------------------------------------------------
// RelationalNet: out[b,h] = ( sum_{i<sl1,j<sl2} relu(y1[b,i,h]+y2[b,j,h]+bias[h])
//                             + (L1*L2 - sl1*sl2) * relu(bias[h]) ) / (sl1*sl2)
// y1 = x1 @ W[:, :512]^T , y2 = x2 @ W[:, 512:]^T
// B=32, L1=L2=64, FEAT=512, H=256
// ---------------------------------------------------------------------------

#define BM 64
#define BN 64
#define BK 32
#define TM 4
#define TN 4

// scratch: y rows [0,2048) = y1 (b*64+i), rows [2048,4096) = y2 (b*64+j)
__device__ float g_Y[4096 * 256];
__device__ float g_partial[8 * 32 * 256];

// swizzled transposed smem index: tile stored as [BK][BM], 16B-group XOR swizzle
__device__ __forceinline__ int swz(int kk, int m) {
    return kk * BM + (((((m >> 2) ^ (kk & 7))) << 2) | (m & 3));
}

__global__ __launch_bounds__(256, 2)
void gemm_kernel(const float* __restrict__ x1, const float* __restrict__ x2,
                 const float* __restrict__ W) {
    __shared__ float Xs[BK * BM];
    __shared__ float Ws[BK * BN];

    const int row0 = blockIdx.x * BM;   // 0..4032 (never straddles 2048)
    const int n0   = blockIdx.y * BN;   // 0..192

    const float* X;
    int woff;
    if (row0 < 2048) { X = x1 + (size_t)row0 * 512;          woff = 0;   }
    else             { X = x2 + (size_t)(row0 - 2048) * 512; woff = 512; }
    const float* Wp = W + (size_t)n0 * 1024 + woff;

    const int t  = threadIdx.x;
    const int kk = t & 31;    // 0..31
    const int mq = t >> 5;    // 0..7
    const int ty = t >> 4;    // 0..15
    const int tx = t & 15;    // 0..15

    float acc[TM][TN];
#pragma unroll
    for (int i = 0; i < TM; i++)
#pragma unroll
        for (int j = 0; j < TN; j++) acc[i][j] = 0.f;

    for (int k0 = 0; k0 < 512; k0 += BK) {
#pragma unroll
        for (int rep = 0; rep < 2; rep++) {
            int mb = (mq + rep * 8) * 4;   // 0,4,...,60
            float4 vx;
            vx.x = X[(size_t)(mb + 0) * 512 + k0 + kk];
            vx.y = X[(size_t)(mb + 1) * 512 + k0 + kk];
            vx.z = X[(size_t)(mb + 2) * 512 + k0 + kk];
            vx.w = X[(size_t)(mb + 3) * 512 + k0 + kk];
            *reinterpret_cast<float4*>(&Xs[swz(kk, mb)]) = vx;
            float4 vw;
            vw.x = Wp[(size_t)(mb + 0) * 1024 + k0 + kk];
            vw.y = Wp[(size_t)(mb + 1) * 1024 + k0 + kk];
            vw.z = Wp[(size_t)(mb + 2) * 1024 + k0 + kk];
            vw.w = Wp[(size_t)(mb + 3) * 1024 + k0 + kk];
            *reinterpret_cast<float4*>(&Ws[swz(kk, mb)]) = vw;
        }
        __syncthreads();

#pragma unroll
        for (int k = 0; k < BK; k++) {
            float4 a = *reinterpret_cast<const float4*>(&Xs[swz(k, ty * 4)]);
            float4 b4 = *reinterpret_cast<const float4*>(&Ws[swz(k, tx * 4)]);
            float av[4] = {a.x, a.y, a.z, a.w};
            float bv[4] = {b4.x, b4.y, b4.z, b4.w};
#pragma unroll
            for (int i = 0; i < TM; i++)
#pragma unroll
                for (int j = 0; j < TN; j++)
                    acc[i][j] = fmaf(av[i], bv[j], acc[i][j]);
        }
        __syncthreads();
    }

#pragma unroll
    for (int i = 0; i < TM; i++) {
        float4 o = make_float4(acc[i][0], acc[i][1], acc[i][2], acc[i][3]);
        *reinterpret_cast<float4*>(&g_Y[(size_t)(row0 + ty * 4 + i) * 256 + n0 + tx * 4]) = o;
    }
}

#define ICHUNK 8

__global__ __launch_bounds__(256)
void pair_kernel(const float* __restrict__ bias,
                 const int* __restrict__ sl1, const int* __restrict__ sl2) {
    extern __shared__ float v[];   // [64][256] = y2[b] + bias
    const int b = blockIdx.x;      // 0..31
    const int c = blockIdx.y;      // 0..7 (i-chunk)
    const int h = threadIdx.x;     // 0..255

    const int n1 = sl1[b];
    const int n2 = sl2[b];
    const float bh = bias[h];
    const float* y2 = &g_Y[(size_t)(2048 + b * 64) * 256];

#pragma unroll 8
    for (int j = 0; j < 64; j++)
        v[j * 256 + h] = y2[(size_t)j * 256 + h] + bh;
    __syncthreads();

    float acc = 0.f;
    const int ibeg = c * ICHUNK;
    const int iend = min(ibeg + ICHUNK, n1);
    for (int i = ibeg; i < iend; i++) {
        const float u = g_Y[(size_t)(b * 64 + i) * 256 + h];
        int j = 0;
        for (; j + 4 <= n2; j += 4) {
            acc += fmaxf(u + v[(j + 0) * 256 + h], 0.f);
            acc += fmaxf(u + v[(j + 1) * 256 + h], 0.f);
            acc += fmaxf(u + v[(j + 2) * 256 + h], 0.f);
            acc += fmaxf(u + v[(j + 3) * 256 + h], 0.f);
        }
        for (; j < n2; j++)
            acc += fmaxf(u + v[j * 256 + h], 0.f);
    }
    g_partial[(size_t)(c * 32 + b) * 256 + h] = acc;
}

__global__ __launch_bounds__(256)
void finalize_kernel(const float* __restrict__ bias,
                     const int* __restrict__ sl1, const int* __restrict__ sl2,
                     float* __restrict__ out) {
    const int idx = blockIdx.x * 256 + threadIdx.x;  // 0..8191
    const int b = idx >> 8;
    const int h = idx & 255;
    float s = 0.f;
#pragma unroll
    for (int c = 0; c < 8; c++)
        s += g_partial[(size_t)(c * 32 + b) * 256 + h];
    const float n = (float)(sl1[b] * sl2[b]);
    const float pad = (4096.f - n) * fmaxf(bias[h], 0.f);
    out[idx] = (s + pad) / n;
}

extern "C" void kernel_launch(void* const* d_in, const int* in_sizes, int n_in,
                              void* d_out, int out_size) {
    const float* x1   = (const float*)d_in[0];
    const int*   sl1  = (const int*)  d_in[1];
    const float* x2   = (const float*)d_in[2];
    const int*   sl2  = (const int*)  d_in[3];
    const float* W    = (const float*)d_in[4];
    const float* bias = (const float*)d_in[5];
    float* out = (float*)d_out;

    // GEMM: M=4096 (x1 rows then x2 rows), N=256, K=512
    dim3 ggrid(4096 / BM, 256 / BN);
    gemm_kernel<<<ggrid, 256>>>(x1, x2, W);

    // pairwise relu-sum over (i,j), partials per i-chunk
    const int smem = 64 * 256 * sizeof(float);   // 64 KB
    cudaFuncSetAttribute(pair_kernel, cudaFuncAttributeMaxDynamicSharedMemorySize, smem);
    dim3 pgrid(32, 8);
    pair_kernel<<<pgrid, 256, smem>>>(bias, sl1, sl2);

    finalize_kernel<<<32, 256>>>(bias, sl1, sl2, out);
}

// round 11
// speedup vs baseline: 1.0137x; 1.0137x over previous
#include <cuda_runtime.h>

// ---------------------------------------------------------------------------
// RelationalNet: out[b,h] = ( sum_{i<sl1,j<sl2} relu(y1[b,i,h]+y2[b,j,h]+bias[h])
//                             + (L1*L2 - sl1*sl2) * relu(bias[h]) ) / (sl1*sl2)
// y1 = x1 @ W[:, :512]^T , y2 = x2 @ W[:, 512:]^T
// B=32, L1=L2=64, FEAT=512, H=256
// ---------------------------------------------------------------------------

#define BM 64
#define BN 64
#define BK 32
#define TM 4
#define TN 4

// scratch: y rows [0,2048) = y1 (b*64+i), rows [2048,4096) = y2 (b*64+j)
__device__ float g_Y[4096 * 256];
__device__ float g_partial[8 * 32 * 256];

// swizzled transposed smem index: tile stored as [BK][BM], 16B-group XOR swizzle
__device__ __forceinline__ int swz(int kk, int m) {
    return kk * BM + (((((m >> 2) ^ (kk & 7))) << 2) | (m & 3));
}

__global__ __launch_bounds__(256, 2)
void gemm_kernel(const float* __restrict__ x1, const float* __restrict__ x2,
                 const float* __restrict__ W) {
    __shared__ float Xs[BK * BM];
    __shared__ float Ws[BK * BN];

    const int row0 = blockIdx.x * BM;   // 0..4032 (never straddles 2048)
    const int n0   = blockIdx.y * BN;   // 0..192

    const float* X;
    int woff;
    if (row0 < 2048) { X = x1 + (size_t)row0 * 512;          woff = 0;   }
    else             { X = x2 + (size_t)(row0 - 2048) * 512; woff = 512; }
    const float* Wp = W + (size_t)n0 * 1024 + woff;

    const int t  = threadIdx.x;
    const int kk = t & 31;    // 0..31
    const int mq = t >> 5;    // 0..7
    const int ty = t >> 4;    // 0..15
    const int tx = t & 15;    // 0..15

    float acc[TM][TN];
#pragma unroll
    for (int i = 0; i < TM; i++)
#pragma unroll
        for (int j = 0; j < TN; j++) acc[i][j] = 0.f;

    for (int k0 = 0; k0 < 512; k0 += BK) {
#pragma unroll
        for (int rep = 0; rep < 2; rep++) {
            int mb = (mq + rep * 8) * 4;   // 0,4,...,60
            float4 vx;
            vx.x = X[(size_t)(mb + 0) * 512 + k0 + kk];
            vx.y = X[(size_t)(mb + 1) * 512 + k0 + kk];
            vx.z = X[(size_t)(mb + 2) * 512 + k0 + kk];
            vx.w = X[(size_t)(mb + 3) * 512 + k0 + kk];
            *reinterpret_cast<float4*>(&Xs[swz(kk, mb)]) = vx;
            float4 vw;
            vw.x = Wp[(size_t)(mb + 0) * 1024 + k0 + kk];
            vw.y = Wp[(size_t)(mb + 1) * 1024 + k0 + kk];
            vw.z = Wp[(size_t)(mb + 2) * 1024 + k0 + kk];
            vw.w = Wp[(size_t)(mb + 3) * 1024 + k0 + kk];
            *reinterpret_cast<float4*>(&Ws[swz(kk, mb)]) = vw;
        }
        __syncthreads();

#pragma unroll
        for (int k = 0; k < BK; k++) {
            float4 a = *reinterpret_cast<const float4*>(&Xs[swz(k, ty * 4)]);
            float4 b4 = *reinterpret_cast<const float4*>(&Ws[swz(k, tx * 4)]);
            float av[4] = {a.x, a.y, a.z, a.w};
            float bv[4] = {b4.x, b4.y, b4.z, b4.w};
#pragma unroll
            for (int i = 0; i < TM; i++)
#pragma unroll
                for (int j = 0; j < TN; j++)
                    acc[i][j] = fmaf(av[i], bv[j], acc[i][j]);
        }
        __syncthreads();
    }

#pragma unroll
    for (int i = 0; i < TM; i++) {
        float4 o = make_float4(acc[i][0], acc[i][1], acc[i][2], acc[i][3]);
        *reinterpret_cast<float4*>(&g_Y[(size_t)(row0 + ty * 4 + i) * 256 + n0 + tx * 4]) = o;
    }
}

#define ICHUNK 8

__global__ __launch_bounds__(256)
void pair_kernel(const float* __restrict__ bias,
                 const int* __restrict__ sl1, const int* __restrict__ sl2) {
    extern __shared__ float v[];   // [64][256] = y2[b] + bias
    const int b = blockIdx.x;      // 0..31
    const int c = blockIdx.y;      // 0..7 (i-chunk)
    const int h = threadIdx.x;     // 0..255

    const int n1 = sl1[b];
    const int n2 = sl2[b];
    const float bh = bias[h];
    const float* y2 = &g_Y[(size_t)(2048 + b * 64) * 256];

#pragma unroll 8
    for (int j = 0; j < 64; j++)
        v[j * 256 + h] = y2[(size_t)j * 256 + h] + bh;
    __syncthreads();

    float acc = 0.f;
    const int ibeg = c * ICHUNK;
    const int iend = min(ibeg + ICHUNK, n1);
    for (int i = ibeg; i < iend; i++) {
        const float u = g_Y[(size_t)(b * 64 + i) * 256 + h];
        int j = 0;
        for (; j + 4 <= n2; j += 4) {
            acc += fmaxf(u + v[(j + 0) * 256 + h], 0.f);
            acc += fmaxf(u + v[(j + 1) * 256 + h], 0.f);
            acc += fmaxf(u + v[(j + 2) * 256 + h], 0.f);
            acc += fmaxf(u + v[(j + 3) * 256 + h], 0.f);
        }
        for (; j < n2; j++)
            acc += fmaxf(u + v[j * 256 + h], 0.f);
    }
    g_partial[(size_t)(c * 32 + b) * 256 + h] = acc;
}

__global__ __launch_bounds__(256)
void finalize_kernel(const float* __restrict__ bias,
                     const int* __restrict__ sl1, const int* __restrict__ sl2,
                     float* __restrict__ out) {
    const int idx = blockIdx.x * 256 + threadIdx.x;  // 0..8191
    const int b = idx >> 8;
    const int h = idx & 255;
    float s = 0.f;
#pragma unroll
    for (int c = 0; c < 8; c++)
        s += g_partial[(size_t)(c * 32 + b) * 256 + h];
    const float n = (float)(sl1[b] * sl2[b]);
    const float pad = (4096.f - n) * fmaxf(bias[h], 0.f);
    out[idx] = (s + pad) / n;
}

extern "C" void kernel_launch(void* const* d_in, const int* in_sizes, int n_in,
                              void* d_out, int out_size) {
    const float* x1   = (const float*)d_in[0];
    const int*   sl1  = (const int*)  d_in[1];
    const float* x2   = (const float*)d_in[2];
    const int*   sl2  = (const int*)  d_in[3];
    const float* W    = (const float*)d_in[4];
    const float* bias = (const float*)d_in[5];
    float* out = (float*)d_out;

    // GEMM: M=4096 (x1 rows then x2 rows), N=256, K=512
    dim3 ggrid(4096 / BM, 256 / BN);
    gemm_kernel<<<ggrid, 256>>>(x1, x2, W);

    // pairwise relu-sum over (i,j), partials per i-chunk
    const int smem = 64 * 256 * sizeof(float);   // 64 KB
    cudaFuncSetAttribute(pair_kernel, cudaFuncAttributeMaxDynamicSharedMemorySize, smem);
    dim3 pgrid(32, 8);
    pair_kernel<<<pgrid, 256, smem>>>(bias, sl1, sl2);

    finalize_kernel<<<32, 256>>>(bias, sl1, sl2, out);
}